// round 15
// baseline (speedup 1.0000x reference)
#include <cuda_runtime.h>
#include <cuda_bf16.h>
#include <cstdint>

#define NEVT 8192
#define NSEVT 16384
#define DIM 128

// ---------------- scratch (__device__ globals: no allocation allowed) -----
__device__ float g_sproj[NSEVT];                       // s_proj * log2(e)
__device__ float g_eproj[NEVT];                        // e_proj * log2(e)
// B (subevent^T) as e4m3 mma-fragments, per 64-k tile: 2048 uint32 (8KB)
__device__ uint32_t g_BF[256 * 2048];                  // 2 MB
__device__ float g_num[2ull * NEVT * DIM];             // split-K numerator partials
__device__ float g_z[2 * NEVT];                        // split-K Z partials (x 2^-5)

// ---------------- helpers ---------------------------------------------------
__device__ __forceinline__ uint32_t smem_u32(const void* p) {
    uint32_t a;
    asm("{ .reg .u64 t; cvta.to.shared.u64 t, %1; cvt.u32.u64 %0, t; }"
        : "=r"(a) : "l"(p));
    return a;
}

__device__ __forceinline__ float ex2f(float x) {   // 2^x
    float y;
    asm("ex2.approx.ftz.f32 %0, %1;" : "=f"(y) : "f"(x));
    return y;
}

// pack 4 floats -> 4 e4m3 bytes (ascending)
__device__ __forceinline__ uint32_t pack_e4m3x4(float a, float b, float c, float d) {
    uint16_t lo, hi;
    asm("cvt.rn.satfinite.e4m3x2.f32 %0, %1, %2;" : "=h"(lo) : "f"(b), "f"(a));
    asm("cvt.rn.satfinite.e4m3x2.f32 %0, %1, %2;" : "=h"(hi) : "f"(d), "f"(c));
    return (uint32_t)lo | ((uint32_t)hi << 16);
}

__device__ __forceinline__ void mma_fp8(float* d, const uint32_t* a,
                                        uint32_t b0, uint32_t b1) {
    asm volatile(
        "mma.sync.aligned.m16n8k32.row.col.f32.e4m3.e4m3.f32 "
        "{%0,%1,%2,%3}, {%4,%5,%6,%7}, {%8,%9}, {%0,%1,%2,%3};"
        : "+f"(d[0]), "+f"(d[1]), "+f"(d[2]), "+f"(d[3])
        : "r"(a[0]), "r"(a[1]), "r"(a[2]), "r"(a[3]), "r"(b0), "r"(b1));
}

__device__ __forceinline__ void bar_named_sync(int id) {
    asm volatile("bar.sync %0, %1;" :: "r"(id), "r"(512) : "memory");
}
__device__ __forceinline__ void bar_named_arrive(int id) {
    asm volatile("bar.arrive %0, %1;" :: "r"(id), "r"(512) : "memory");
}

// ---------------- kernel 1: projections (scaled by log2 e) ------------------
__global__ void proj_kernel(const float* __restrict__ sub,
                            const float* __restrict__ evt,
                            const float* __restrict__ w) {
    const float L = 1.4426950408889634f;
    int gw = (blockIdx.x * blockDim.x + threadIdx.x) >> 5;
    int lane = threadIdx.x & 31;
    int nw = (gridDim.x * blockDim.x) >> 5;
    for (int r = gw; r < NSEVT + NEVT; r += nw) {
        const float* base;
        const float* wp;
        if (r < NSEVT) { base = sub + (size_t)r * DIM; wp = w; }
        else           { base = evt + (size_t)(r - NSEVT) * DIM; wp = w + DIM; }
        float4 v = ((const float4*)base)[lane];
        float4 ww = __ldg((const float4*)wp + lane);
        float d = v.x * ww.x + v.y * ww.y + v.z * ww.z + v.w * ww.w;
        #pragma unroll
        for (int o = 16; o; o >>= 1) d += __shfl_xor_sync(0xffffffffu, d, o);
        if (lane == 0) {
            if (r < NSEVT) g_sproj[r] = d * L;
            else           g_eproj[r - NSEVT] = d * L;
        }
    }
}

// ---------------- kernel 2: subevent -> e4m3 B-fragments --------------------
__global__ void bfrag_kernel(const float* __restrict__ sub) {
    __shared__ float smf[64][132];          // padded rows
    const int t = threadIdx.x;              // 256 threads
    const int kt = blockIdx.x;              // 0..255 (global 64-k tile)
    const int jl = t >> 2;                  // row 0..63
    const int cb = t & 3;
    const float4* src = (const float4*)(sub + (size_t)(kt * 64 + jl) * DIM);
    #pragma unroll
    for (int it = 0; it < 8; ++it) {
        float4 v = src[cb + it * 4];
        int d = (cb + it * 4) * 4;
        smf[jl][d + 0] = v.x; smf[jl][d + 1] = v.y;
        smf[jl][d + 2] = v.z; smf[jl][d + 3] = v.w;
    }
    __syncthreads();
    uint32_t* dst = g_BF + (size_t)kt * 2048;
    #pragma unroll
    for (int i = 0; i < 8; ++i) {
        int idx = t + i * 256;
        int j = idx & 3, lane = (idx >> 2) & 31, p = (idx >> 7) & 3;
        int half = (idx >> 9) & 1, ks = idx >> 10;
        int n = half * 64 + (p * 2 + (j >> 1)) * 8 + (lane >> 2);
        int kb = ks * 32 + (j & 1) * 16 + (lane & 3) * 4;
        dst[idx] = pack_e4m3x4(smf[kb][n], smf[kb + 1][n], smf[kb + 2][n], smf[kb + 3][n]);
    }
}

// ---------------- probe: no-op to steer ncu capture onto main_kernel --------
__global__ void probe_kernel() {}

// ---------------- kernel 3: warp-specialized fused softmax-GEMM (fp8) -------
// grid 128 (64 row-tiles x 2 k-halves), 512 threads.
// warps 0-7: consumers (LDS.128 fragments + mma fp8 m16n8k32).
// warps 8-15: producers (adj LDG stream w/ pointer-bump addressing, exp2(t-5),
//             fragment STS, producer-side Z accumulation of e).
// Named HW barriers (count 512): full[s] = 1+s, empty[s] = 1+NSTAGE+s.
// smem: [0,32768) sproj; stages of 16KB (A-frag 8KB + B-frag 8KB)
#define SP_OFF   0
#define ST_OFF   33024
#define A_SZ     8192
#define STAGE_SZ 16384
#define NSTAGE   7
#define SMEM_BYTES (ST_OFF + NSTAGE * STAGE_SZ)

__global__ void __launch_bounds__(512, 1)
main_kernel(const float* __restrict__ adj) {
    extern __shared__ char smem[];
    const int tid = threadIdx.x;
    const int wid = tid >> 5;
    const int lid = tid & 31;

    const int tile = blockIdx.x >> 1;
    const int kv_half = blockIdx.x & 1;
    const int i0 = tile * 128;
    const int k0 = kv_half * (NSEVT / 2);

    // cooperative sproj load (all 512 threads)
    {
        float4* spd = (float4*)(smem + SP_OFF);
        const float4* sps = (const float4*)(g_sproj + k0);
        for (int i = tid; i < 2048; i += 512) spd[i] = __ldg(sps + i);
    }
    __syncthreads();

    if (wid >= 8) {
        // =================== PRODUCER ===================
        const int pw = wid - 8;          // 0..7
        const int ptid = tid - 256;      // 0..255
        const int h = lid >> 4;          // half-warp
        const int c4 = lid & 15;         // float4 column slot within 64-col tile
        const int rbase = pw * 2 + h;    // row for i=0 (rows: i*16+rbase)

        // adj byte pointer, bumped 256B per tile; row i at +i*1MB immediate
        const char* ap = (const char*)adj
            + ((size_t)(i0 + rbase) * NSEVT + (size_t)k0) * 4 + (size_t)c4 * 16;
        const char* bfbase = (const char*)g_BF + (size_t)(kv_half * 128) * 8192 + ptid * 32;
        const float4* sp4 = (const float4*)(smem + SP_OFF);

        float epArr[8];
        float zrow[8];
        #pragma unroll
        for (int i = 0; i < 8; ++i) {
            epArr[i] = g_eproj[i0 + i * 16 + rbase];
            zrow[i] = 0.f;
        }

        // A fragment store address (fixed per thread, +i*1024 per row group)
        const uint32_t lane_a = (uint32_t)(rbase & 7) * 4u + (uint32_t)(c4 & 3);
        const uint32_t rsel = ((uint32_t)(c4 >> 2) & 1u) * 2u + ((uint32_t)(rbase >> 3) & 1u);
        const uint32_t ast = ((uint32_t)(c4 >> 3)) * 512u + lane_a * 16u + rsel * 4u;
        const uint32_t bst = (uint32_t)ptid * 32u;

        float4 areg[8];
        #pragma unroll
        for (int i = 0; i < 8; ++i)
            areg[i] = __ldg((const float4*)(ap + (size_t)i * 1048576));

        // B(0) prefetch into regs (L2-resident)
        uint4 bv0 = __ldg((const uint4*)bfbase);
        uint4 bv1 = __ldg((const uint4*)(bfbase + 16));

        int st = 0;

        for (int kt = 0; kt < 128; ++kt) {
            float4 s = sp4[kt * 16 + c4];

            // exp2(adj*f(c) - 5): W scaled by 2^-5 (Z scaled identically)
            uint32_t wpk[8];
            #pragma unroll
            for (int i = 0; i < 8; ++i) {
                float4 a = areg[i];
                float ep = epArr[i];
                float c0 = ep + s.x, c1 = ep + s.y, c2 = ep + s.z, c3 = ep + s.w;
                float f0 = fmaxf(c0, 0.2f * c0), f1 = fmaxf(c1, 0.2f * c1);
                float f2 = fmaxf(c2, 0.2f * c2), f3 = fmaxf(c3, 0.2f * c3);
                float e0 = ex2f(fmaf(a.x, f0, -5.0f));
                float e1 = ex2f(fmaf(a.y, f1, -5.0f));
                float e2 = ex2f(fmaf(a.z, f2, -5.0f));
                float e3 = ex2f(fmaf(a.w, f3, -5.0f));
                zrow[i] += (e0 + e1) + (e2 + e3);      // Z = sum of e (no adj!)
                wpk[i] = pack_e4m3x4(e0 * a.x, e1 * a.y, e2 * a.z, e3 * a.w);
            }

            // prefetch adj(kt+1): pointer bump + constant immediate offsets
            ap += 256;
            if (kt < 127) {
                #pragma unroll
                for (int i = 0; i < 8; ++i)
                    areg[i] = __ldg((const float4*)(ap + (size_t)i * 1048576));
            }

            // stage free? (first NSTAGE stages start free)
            if (kt >= NSTAGE) bar_named_sync(1 + NSTAGE + st);

            char* Ab = smem + ST_OFF + (size_t)st * STAGE_SZ;
            #pragma unroll
            for (int i = 0; i < 8; ++i)
                *reinterpret_cast<uint32_t*>(Ab + ast + i * 1024) = wpk[i];
            *reinterpret_cast<uint4*>(Ab + A_SZ + bst) = bv0;
            *reinterpret_cast<uint4*>(Ab + A_SZ + bst + 16) = bv1;

            bar_named_arrive(1 + st);          // publish full[st]

            // B(kt+1) prefetch (consumed at next tile's store)
            if (kt < 127) {
                const char* bs = bfbase + (size_t)(kt + 1) * 8192;
                bv0 = __ldg((const uint4*)bs);
                bv1 = __ldg((const uint4*)(bs + 16));
            }

            if (++st == NSTAGE) st = 0;
        }

        // Z: reduce across 16-lane column groups, one row per group
        #pragma unroll
        for (int i = 0; i < 8; ++i) {
            float z = zrow[i];
            z += __shfl_xor_sync(0xffffffffu, z, 8);
            z += __shfl_xor_sync(0xffffffffu, z, 4);
            z += __shfl_xor_sync(0xffffffffu, z, 2);
            z += __shfl_xor_sync(0xffffffffu, z, 1);
            if (c4 == 0)
                g_z[(size_t)kv_half * NEVT + i0 + i * 16 + rbase] = z;
        }

    } else {
        // =================== CONSUMER ===================
        const int mwarp = wid & 3;
        const int nhalf = wid >> 2;
        const int m0 = mwarp * 32;
        const int n0 = nhalf * 64;

        float acc[2][8][4];
        #pragma unroll
        for (int mt = 0; mt < 2; ++mt)
            #pragma unroll
            for (int nb = 0; nb < 8; ++nb)
                #pragma unroll
                for (int q = 0; q < 4; ++q) acc[mt][nb][q] = 0.f;

        int st = 0;

        for (int kt = 0; kt < 128; ++kt) {
            bar_named_sync(1 + st);   // full[st]

            const char* Asm = smem + ST_OFF + (size_t)st * STAGE_SZ;
            const char* Bsm = Asm + A_SZ;
            #pragma unroll
            for (int ks = 0; ks < 2; ++ks) {
                uint4 A0 = *reinterpret_cast<const uint4*>(
                    Asm + (mwarp * 4 + ks) * 512 + lid * 16);
                uint4 A1 = *reinterpret_cast<const uint4*>(
                    Asm + (mwarp * 4 + 2 + ks) * 512 + lid * 16);
                uint4 Bq[4];
                #pragma unroll
                for (int p = 0; p < 4; ++p)
                    Bq[p] = *reinterpret_cast<const uint4*>(
                        Bsm + ((ks * 2 + nhalf) * 4 + p) * 512 + lid * 16);

                uint32_t af0[4] = {A0.x, A0.y, A0.z, A0.w};
                uint32_t af1[4] = {A1.x, A1.y, A1.z, A1.w};
                #pragma unroll
                for (int p = 0; p < 4; ++p) {
                    mma_fp8(acc[0][2 * p],     af0, Bq[p].x, Bq[p].y);
                    mma_fp8(acc[0][2 * p + 1], af0, Bq[p].z, Bq[p].w);
                    mma_fp8(acc[1][2 * p],     af1, Bq[p].x, Bq[p].y);
                    mma_fp8(acc[1][2 * p + 1], af1, Bq[p].z, Bq[p].w);
                }
            }

            bar_named_arrive(1 + NSTAGE + st);  // empty[st]
            if (++st == NSTAGE) st = 0;
        }

        // numerator partial writeout (scaled by 2^-5, cancels with Z)
        float* base = g_num + (size_t)kv_half * NEVT * DIM;
        const int r01 = i0 + m0 + (lid >> 2);
        const int colb = n0 + (lid & 3) * 2;
        #pragma unroll
        for (int mt = 0; mt < 2; ++mt) {
            #pragma unroll
            for (int nb = 0; nb < 8; ++nb) {
                int rr = r01 + mt * 16;
                int cc = colb + nb * 8;
                float2 lo = make_float2(acc[mt][nb][0], acc[mt][nb][1]);
                float2 hi = make_float2(acc[mt][nb][2], acc[mt][nb][3]);
                *reinterpret_cast<float2*>(base + (size_t)rr * DIM + cc) = lo;
                *reinterpret_cast<float2*>(base + (size_t)(rr + 8) * DIM + cc) = hi;
            }
        }
    }
}

// ---------------- kernel 4: combine split-K + epilogue ----------------------
__global__ void finalize_kernel(const float* __restrict__ evt, float* __restrict__ out) {
    int idx = blockIdx.x * blockDim.x + threadIdx.x;   // float4 index
    if (idx >= NEVT * (DIM / 4)) return;
    int i = idx >> 5;                                   // row
    float z = g_z[i] + g_z[NEVT + i];
    float inv = 1.0f / z;
    float4 n0 = *((const float4*)g_num + idx);
    float4 n1 = *((const float4*)g_num + (size_t)NEVT * (DIM / 4) + idx);
    float4 e = __ldg((const float4*)evt + idx);
    float4 o;
    o.x = (e.x + (n0.x + n1.x) * inv) * 0.5f;
    o.y = (e.y + (n0.y + n1.y) * inv) * 0.5f;
    o.z = (e.z + (n0.z + n1.z) * inv) * 0.5f;
    o.w = (e.w + (n0.w + n1.w) * inv) * 0.5f;
    ((float4*)out)[idx] = o;
}

// ---------------- launch ----------------------------------------------------
extern "C" void kernel_launch(void* const* d_in, const int* in_sizes, int n_in,
                              void* d_out, int out_size) {
    const float *adj = nullptr, *sub = nullptr, *evt = nullptr, *w = nullptr;
    for (int i = 0; i < n_in; ++i) {
        switch (in_sizes[i]) {
            case NEVT * NSEVT: adj = (const float*)d_in[i]; break;
            case NSEVT * DIM:  sub = (const float*)d_in[i]; break;
            case NEVT * DIM:   evt = (const float*)d_in[i]; break;
            case 2 * DIM:      w   = (const float*)d_in[i]; break;
            default: break;
        }
    }
    (void)out_size;

    static int configured = 0;
    if (!configured) {
        cudaFuncSetAttribute(main_kernel, cudaFuncAttributeMaxDynamicSharedMemorySize,
                             SMEM_BYTES);
        configured = 1;
    }

    proj_kernel<<<96, 256>>>(sub, evt, w);
    bfrag_kernel<<<256, 256>>>(sub);
    probe_kernel<<<1, 32>>>();     // keeps ncu capture aligned on main_kernel
    main_kernel<<<128, 512, SMEM_BYTES>>>(adj);
    finalize_kernel<<<(NEVT * (DIM / 4) + 255) / 256, 256>>>(evt, (float*)d_out);
}

// round 16
// speedup vs baseline: 1.1062x; 1.1062x over previous
#include <cuda_runtime.h>
#include <cuda_bf16.h>
#include <cstdint>

#define NEVT 8192
#define NSEVT 16384
#define DIM 128

// ---------------- scratch (__device__ globals: no allocation allowed) -----
__device__ float g_sproj[NSEVT];                       // s_proj * log2(e)
__device__ float g_eproj[NEVT];                        // e_proj * log2(e)
// subevent^T in bf16, TILE-MAJOR: [ktile = j/64][d = 0..127][j%64]
__device__ __nv_bfloat16 g_ST[(size_t)DIM * NSEVT];
__device__ float g_num[2ull * NEVT * DIM];             // split-K numerator partials
__device__ float g_z[2 * NEVT];                        // split-K Z partials
__device__ int g_flag[64];                             // per-row-tile rendezvous (self-reset)

// ---------------- helpers ---------------------------------------------------
__device__ __forceinline__ uint32_t smem_u32(const void* p) {
    uint32_t a;
    asm("{ .reg .u64 t; cvta.to.shared.u64 t, %1; cvt.u32.u64 %0, t; }"
        : "=r"(a) : "l"(p));
    return a;
}

__device__ __forceinline__ uint32_t pack_bf16x2(float lo, float hi) {
    uint32_t r;
    asm("cvt.rn.bf16x2.f32 %0, %1, %2;" : "=r"(r) : "f"(hi), "f"(lo));
    return r;
}

__device__ __forceinline__ float ex2f(float x) {   // 2^x
    float y;
    asm("ex2.approx.ftz.f32 %0, %1;" : "=f"(y) : "f"(x));
    return y;
}

__device__ __forceinline__ void ldm_x4(uint32_t addr, uint32_t* r) {
    asm volatile("ldmatrix.sync.aligned.m8n8.x4.shared.b16 {%0,%1,%2,%3}, [%4];"
                 : "=r"(r[0]), "=r"(r[1]), "=r"(r[2]), "=r"(r[3]) : "r"(addr));
}

__device__ __forceinline__ void mma16816(float* d, const uint32_t* a, const uint32_t* b) {
    asm volatile(
        "mma.sync.aligned.m16n8k16.row.col.f32.bf16.bf16.f32 "
        "{%0,%1,%2,%3}, {%4,%5,%6,%7}, {%8,%9}, {%0,%1,%2,%3};"
        : "+f"(d[0]), "+f"(d[1]), "+f"(d[2]), "+f"(d[3])
        : "r"(a[0]), "r"(a[1]), "r"(a[2]), "r"(a[3]), "r"(b[0]), "r"(b[1]));
}

__device__ __forceinline__ void mbar_init(uint32_t a, uint32_t cnt) {
    asm volatile("mbarrier.init.shared.b64 [%0], %1;" :: "r"(a), "r"(cnt) : "memory");
}
__device__ __forceinline__ void mbar_arrive(uint32_t a) {
    asm volatile("mbarrier.arrive.shared.b64 _, [%0];" :: "r"(a) : "memory");
}
__device__ __forceinline__ void mbar_wait(uint32_t a, uint32_t parity) {
    asm volatile(
        "{\n\t.reg .pred P;\n\t"
        "WAITLP_%=:\n\t"
        "mbarrier.try_wait.parity.acquire.cta.shared::cta.b64 P, [%0], %1, 0x989680;\n\t"
        "@P bra.uni WAITDN_%=;\n\t"
        "bra.uni WAITLP_%=;\n\t"
        "WAITDN_%=:\n\t}"
        :: "r"(a), "r"(parity) : "memory");
}

// ---------------- kernel 1: transpose (blocks 0-255) + projections (256+) ---
__global__ void pre_kernel(const float* __restrict__ sub,
                           const float* __restrict__ evt,
                           const float* __restrict__ w) {
    __shared__ __nv_bfloat16 smT[128][72];  // 144B rows (transpose branch only)
    const int t = threadIdx.x;              // 256 threads
    if (blockIdx.x < 256) {
        // ---- subevent -> bf16 transpose, tile-major ----
        int j0 = blockIdx.x * 64;
        int jl = t >> 2;
        int sbase = t & 3;
        const float4* src = (const float4*)(sub + (size_t)(j0 + jl) * DIM);
        #pragma unroll
        for (int it = 0; it < 8; ++it) {
            int s = sbase + it * 4;
            float4 v = src[s];
            int d = s * 4;
            smT[d + 0][jl] = __float2bfloat16(v.x);
            smT[d + 1][jl] = __float2bfloat16(v.y);
            smT[d + 2][jl] = __float2bfloat16(v.z);
            smT[d + 3][jl] = __float2bfloat16(v.w);
        }
        __syncthreads();
        int d = t >> 1;
        int jh = (t & 1) * 32;
        uint4* dst = (uint4*)(g_ST + (size_t)blockIdx.x * (128 * 64) + d * 64 + jh);
        const uint4* s4 = (const uint4*)&smT[d][jh];
        dst[0] = s4[0]; dst[1] = s4[1]; dst[2] = s4[2]; dst[3] = s4[3];
    } else {
        // ---- projections, scaled by log2(e) ----
        const float L = 1.4426950408889634f;
        int gw = ((blockIdx.x - 256) * 256 + t) >> 5;
        int lane = t & 31;
        int nw = (96 * 256) >> 5;
        for (int r = gw; r < NSEVT + NEVT; r += nw) {
            const float* base;
            const float* wp;
            if (r < NSEVT) { base = sub + (size_t)r * DIM; wp = w; }
            else           { base = evt + (size_t)(r - NSEVT) * DIM; wp = w + DIM; }
            float4 v = ((const float4*)base)[lane];
            float4 ww = __ldg((const float4*)wp + lane);
            float dsum = v.x * ww.x + v.y * ww.y + v.z * ww.z + v.w * ww.w;
            #pragma unroll
            for (int o = 16; o; o >>= 1) dsum += __shfl_xor_sync(0xffffffffu, dsum, o);
            if (lane == 0) {
                if (r < NSEVT) g_sproj[r] = dsum * L;
                else           g_eproj[r - NSEVT] = dsum * L;
            }
        }
    }
}

// ---------------- kernel 2: warp-specialized fused softmax-GEMM + epilogue --
// grid 128 (64 row-tiles x 2 k-halves), 512 threads.  (R7-proven mainloop)
// warps 0-7: consumers (ldmatrix + mma bf16).  warps 8-15: producers.
// Tail: second-finishing CTA of each row-tile pair computes out rows.
#define SP_OFF   0
#define BAR_OFF  32768
#define BCAST_OFF 33000
#define ST_OFF   33536
#define STAGE_SZ 36864
#define A_SZ     18432
#define NSTAGE   3
#define SMEM_BYTES (ST_OFF + NSTAGE * STAGE_SZ)

__global__ void __launch_bounds__(512, 1)
main_kernel(const float* __restrict__ adj,
            const float* __restrict__ evt,
            float* __restrict__ out) {
    extern __shared__ char smem[];
    const int tid = threadIdx.x;
    const int wid = tid >> 5;
    const int lid = tid & 31;

    const int tile = blockIdx.x >> 1;
    const int kv_half = blockIdx.x & 1;
    const int i0 = tile * 128;
    const int k0 = kv_half * (NSEVT / 2);

    const uint32_t sb = smem_u32(smem);

    // cooperative sproj load (all 512 threads)
    {
        float4* spd = (float4*)(smem + SP_OFF);
        const float4* sps = (const float4*)(g_sproj + k0);
        for (int i = tid; i < 2048; i += 512) spd[i] = __ldg(sps + i);
    }
    if (tid == 0) {
        #pragma unroll
        for (int s = 0; s < NSTAGE; ++s) {
            mbar_init(sb + BAR_OFF + s * 16, 256);      // full[s]: 256 producers
            mbar_init(sb + BAR_OFF + s * 16 + 8, 256);  // empty[s]: 256 consumers
        }
    }
    __syncthreads();

    if (wid >= 8) {
        // =================== PRODUCER (coalesced) ===================
        const int pw = wid - 8;          // 0..7
        const int ptid = tid - 256;      // 0..255
        const int h = lid >> 4;          // half-warp
        const int c4 = lid & 15;         // float4 column slot within 64-col tile
        const int rbase = pw * 2 + h;    // row for iteration i=0 (rows: i*16+rbase)

        const float4* a4p = (const float4*)(adj + (size_t)(i0 + rbase) * NSEVT + k0) + c4;
        const char* gstb = (const char*)g_ST + (size_t)(kv_half * 128) * 16384 + ptid * 16;
        const float4* sp4 = (const float4*)(smem + SP_OFF);

        float epArr[8];
        float zrow[8];
        #pragma unroll
        for (int i = 0; i < 8; ++i) {
            epArr[i] = g_eproj[i0 + i * 16 + rbase];
            zrow[i] = 0.f;
        }

        const uint32_t bst_base = (uint32_t)(ptid >> 3) * 144u + (uint32_t)(ptid & 7) * 16u;
        const uint32_t ast_base = (uint32_t)rbase * 144u + (uint32_t)c4 * 8u;

        float4 areg[8];
        #pragma unroll
        for (int i = 0; i < 8; ++i) areg[i] = __ldg(a4p + (size_t)i * 65536);

        int st = 0, ph = 1;   // producer parity starts at 1: first empty-wait passes

        for (int kt = 0; kt < 128; ++kt) {
            // B tile loads (lane-contiguous)
            uint4 bv[4];
            {
                const char* bsrc = gstb + (size_t)kt * 16384;
                #pragma unroll
                for (int j = 0; j < 4; ++j)
                    bv[j] = __ldg((const uint4*)(bsrc + j * 4096));
            }

            float4 s = sp4[kt * 16 + c4];

            // exp compute into wpk (consumes areg), accumulate per-row Z
            uint2 wpk[8];
            #pragma unroll
            for (int i = 0; i < 8; ++i) {
                float4 a = areg[i];
                float ep = epArr[i];
                float c0 = ep + s.x, c1 = ep + s.y, c2 = ep + s.z, c3 = ep + s.w;
                float f0 = fmaxf(c0, 0.2f * c0), f1 = fmaxf(c1, 0.2f * c1);
                float f2 = fmaxf(c2, 0.2f * c2), f3 = fmaxf(c3, 0.2f * c3);
                float e0 = ex2f(a.x * f0), e1 = ex2f(a.y * f1);
                float e2 = ex2f(a.z * f2), e3 = ex2f(a.w * f3);
                zrow[i] += (e0 + e1) + (e2 + e3);
                wpk[i].x = pack_bf16x2(e0 * a.x, e1 * a.y);
                wpk[i].y = pack_bf16x2(e2 * a.z, e3 * a.w);
            }

            // prefetch next adj tile (areg free now)
            if (kt < 127) {
                const float4* anext = a4p + (kt + 1) * 16;
                #pragma unroll
                for (int i = 0; i < 8; ++i) areg[i] = __ldg(anext + (size_t)i * 65536);
            }

            // wait for stage free, store A + B, publish
            mbar_wait(sb + BAR_OFF + st * 16 + 8, ph);
            {
                char* Ab = smem + ST_OFF + (size_t)st * STAGE_SZ;
                char* Bb = Ab + A_SZ;
                #pragma unroll
                for (int i = 0; i < 8; ++i)
                    *reinterpret_cast<uint2*>(Ab + ast_base + i * (16 * 144)) = wpk[i];
                #pragma unroll
                for (int j = 0; j < 4; ++j)
                    *reinterpret_cast<uint4*>(Bb + bst_base + j * (32 * 144)) = bv[j];
            }
            mbar_arrive(sb + BAR_OFF + st * 16);   // full[st]

            if (++st == NSTAGE) { st = 0; ph ^= 1; }
        }

        // Z: reduce across 16-lane column groups, one row per group
        #pragma unroll
        for (int i = 0; i < 8; ++i) {
            float z = zrow[i];
            z += __shfl_xor_sync(0xffffffffu, z, 8);
            z += __shfl_xor_sync(0xffffffffu, z, 4);
            z += __shfl_xor_sync(0xffffffffu, z, 2);
            z += __shfl_xor_sync(0xffffffffu, z, 1);
            if (c4 == 0)
                g_z[(size_t)kv_half * NEVT + i0 + i * 16 + rbase] = z;
        }

    } else {
        // =================== CONSUMER ===================
        const int m0 = (wid & 3) * 32;
        const int n0 = (wid >> 2) * 64;
        const uint32_t a_radd = (uint32_t)(lid & 15) * 144u + ((uint32_t)(lid >> 4) * 8u) * 2u;
        const uint32_t b_radd = ((uint32_t)(lid & 7) + ((uint32_t)(lid >> 4) & 1u) * 8u) * 144u
                              + (((uint32_t)(lid >> 3) & 1u) * 8u) * 2u;

        float acc[2][8][4];
        #pragma unroll
        for (int mt = 0; mt < 2; ++mt)
            #pragma unroll
            for (int nb = 0; nb < 8; ++nb)
                #pragma unroll
                for (int q = 0; q < 4; ++q) acc[mt][nb][q] = 0.f;

        int st = 0, ph = 0;

        for (int kt = 0; kt < 128; ++kt) {
            mbar_wait(sb + BAR_OFF + st * 16, ph);   // full[st]

            const uint32_t Asb = sb + ST_OFF + (uint32_t)st * STAGE_SZ;
            const uint32_t Bsb = Asb + A_SZ;
            #pragma unroll
            for (int ks = 0; ks < 4; ++ks) {
                uint32_t afr[2][4];
                ldm_x4(Asb + (uint32_t)(m0)      * 144u + (uint32_t)(ks * 16) * 2u + a_radd, afr[0]);
                ldm_x4(Asb + (uint32_t)(m0 + 16) * 144u + (uint32_t)(ks * 16) * 2u + a_radd, afr[1]);
                uint32_t bfr[8][2];
                #pragma unroll
                for (int q = 0; q < 4; ++q) {
                    uint32_t t[4];
                    ldm_x4(Bsb + (uint32_t)(n0 + 16 * q) * 144u + (uint32_t)(ks * 16) * 2u + b_radd, t);
                    bfr[2 * q][0] = t[0]; bfr[2 * q][1] = t[1];
                    bfr[2 * q + 1][0] = t[2]; bfr[2 * q + 1][1] = t[3];
                }
                #pragma unroll
                for (int mt = 0; mt < 2; ++mt)
                    #pragma unroll
                    for (int nb = 0; nb < 8; ++nb)
                        mma16816(acc[mt][nb], afr[mt], bfr[nb]);
            }

            mbar_arrive(sb + BAR_OFF + st * 16 + 8);  // empty[st]
            if (++st == NSTAGE) { st = 0; ph ^= 1; }
        }

        // numerator partial writeout
        float* base = g_num + (size_t)kv_half * NEVT * DIM;
        const int r01 = i0 + m0 + (lid >> 2);
        const int colb = n0 + (lid & 3) * 2;
        #pragma unroll
        for (int mt = 0; mt < 2; ++mt) {
            #pragma unroll
            for (int nb = 0; nb < 8; ++nb) {
                int rr = r01 + mt * 16;
                int cc = colb + nb * 8;
                float2 lo = make_float2(acc[mt][nb][0], acc[mt][nb][1]);
                float2 hi = make_float2(acc[mt][nb][2], acc[mt][nb][3]);
                *reinterpret_cast<float2*>(base + (size_t)rr * DIM + cc) = lo;
                *reinterpret_cast<float2*>(base + (size_t)(rr + 8) * DIM + cc) = hi;
            }
        }
    }

    // =================== fused epilogue (split-K combine) ===================
    // Release: every thread fences its own global writes, then rendezvous.
    __threadfence();
    __syncthreads();
    if (tid == 0) {
        int old = atomicAdd(&g_flag[tile], 1);
        *reinterpret_cast<int*>(smem + BCAST_OFF) = old;
    }
    __syncthreads();
    if (*reinterpret_cast<int*>(smem + BCAST_OFF) == 1) {
        __threadfence();   // acquire partner CTA's g_num/g_z writes
        const float4* numA = (const float4*)g_num + (size_t)i0 * 32;
        const float4* numB = (const float4*)(g_num + (size_t)NEVT * DIM) + (size_t)i0 * 32;
        const float4* ev4  = (const float4*)evt + (size_t)i0 * 32;
        float4* o4 = (float4*)out + (size_t)i0 * 32;
        for (int idx = tid; idx < 128 * 32; idx += 512) {
            int r = idx >> 5;
            float z = g_z[i0 + r] + g_z[NEVT + i0 + r];
            float inv = 1.0f / z;
            float4 n0 = numA[idx];
            float4 n1 = numB[idx];
            float4 e = __ldg(ev4 + idx);
            float4 o;
            o.x = (e.x + (n0.x + n1.x) * inv) * 0.5f;
            o.y = (e.y + (n0.y + n1.y) * inv) * 0.5f;
            o.z = (e.z + (n0.z + n1.z) * inv) * 0.5f;
            o.w = (e.w + (n0.w + n1.w) * inv) * 0.5f;
            o4[idx] = o;
        }
        if (tid == 0) g_flag[tile] = 0;   // reset for next graph replay
    }
}

// ---------------- launch ----------------------------------------------------
extern "C" void kernel_launch(void* const* d_in, const int* in_sizes, int n_in,
                              void* d_out, int out_size) {
    const float *adj = nullptr, *sub = nullptr, *evt = nullptr, *w = nullptr;
    for (int i = 0; i < n_in; ++i) {
        switch (in_sizes[i]) {
            case NEVT * NSEVT: adj = (const float*)d_in[i]; break;
            case NSEVT * DIM:  sub = (const float*)d_in[i]; break;
            case NEVT * DIM:   evt = (const float*)d_in[i]; break;
            case 2 * DIM:      w   = (const float*)d_in[i]; break;
            default: break;
        }
    }
    (void)out_size;

    static int configured = 0;
    if (!configured) {
        cudaFuncSetAttribute(main_kernel, cudaFuncAttributeMaxDynamicSharedMemorySize,
                             SMEM_BYTES);
        configured = 1;
    }

    pre_kernel<<<352, 256>>>(sub, evt, w);
    main_kernel<<<128, 512, SMEM_BYTES>>>(adj, evt, (float*)d_out);
}

// round 17
// speedup vs baseline: 1.1674x; 1.0553x over previous
#include <cuda_runtime.h>
#include <cuda_bf16.h>
#include <cstdint>

#define NEVT 8192
#define NSEVT 16384
#define DIM 128

// ---------------- scratch (__device__ globals: no allocation allowed) -----
__device__ float g_sproj[NSEVT];                       // s_proj * log2(e)
__device__ float g_eproj[NEVT];                        // e_proj * log2(e)
// subevent^T in bf16, TILE-MAJOR: [ktile = j/64][d = 0..127][j%64]
__device__ __nv_bfloat16 g_ST[(size_t)DIM * NSEVT];
__device__ float g_num[2ull * NEVT * DIM];             // split-K numerator partials
__device__ float g_z[2 * NEVT];                        // split-K Z partials
__device__ int g_flag[64];                             // per-row-tile rendezvous (self-reset)

// ---------------- helpers ---------------------------------------------------
__device__ __forceinline__ uint32_t smem_u32(const void* p) {
    uint32_t a;
    asm("{ .reg .u64 t; cvta.to.shared.u64 t, %1; cvt.u32.u64 %0, t; }"
        : "=r"(a) : "l"(p));
    return a;
}

__device__ __forceinline__ uint32_t pack_bf16x2(float lo, float hi) {
    uint32_t r;
    asm("cvt.rn.bf16x2.f32 %0, %1, %2;" : "=r"(r) : "f"(hi), "f"(lo));
    return r;
}

__device__ __forceinline__ float ex2f(float x) {   // 2^x
    float y;
    asm("ex2.approx.ftz.f32 %0, %1;" : "=f"(y) : "f"(x));
    return y;
}

__device__ __forceinline__ void ldm_x4(uint32_t addr, uint32_t* r) {
    asm volatile("ldmatrix.sync.aligned.m8n8.x4.shared.b16 {%0,%1,%2,%3}, [%4];"
                 : "=r"(r[0]), "=r"(r[1]), "=r"(r[2]), "=r"(r[3]) : "r"(addr));
}

__device__ __forceinline__ void mma16816(float* d, const uint32_t* a, const uint32_t* b) {
    asm volatile(
        "mma.sync.aligned.m16n8k16.row.col.f32.bf16.bf16.f32 "
        "{%0,%1,%2,%3}, {%4,%5,%6,%7}, {%8,%9}, {%0,%1,%2,%3};"
        : "+f"(d[0]), "+f"(d[1]), "+f"(d[2]), "+f"(d[3])
        : "r"(a[0]), "r"(a[1]), "r"(a[2]), "r"(a[3]), "r"(b[0]), "r"(b[1]));
}

__device__ __forceinline__ void mbar_init(uint32_t a, uint32_t cnt) {
    asm volatile("mbarrier.init.shared.b64 [%0], %1;" :: "r"(a), "r"(cnt) : "memory");
}
__device__ __forceinline__ void mbar_arrive(uint32_t a) {
    asm volatile("mbarrier.arrive.shared.b64 _, [%0];" :: "r"(a) : "memory");
}
__device__ __forceinline__ void mbar_wait(uint32_t a, uint32_t parity) {
    asm volatile(
        "{\n\t.reg .pred P;\n\t"
        "WAITLP_%=:\n\t"
        "mbarrier.try_wait.parity.acquire.cta.shared::cta.b64 P, [%0], %1, 0x989680;\n\t"
        "@P bra.uni WAITDN_%=;\n\t"
        "bra.uni WAITLP_%=;\n\t"
        "WAITDN_%=:\n\t}"
        :: "r"(a), "r"(parity) : "memory");
}

// ---------------- kernel 1: transpose (blocks 0-255) + projections (256+) ---
__global__ void pre_kernel(const float* __restrict__ sub,
                           const float* __restrict__ evt,
                           const float* __restrict__ w) {
    __shared__ __nv_bfloat16 smT[128][72];  // 144B rows (transpose branch only)
    const int t = threadIdx.x;              // 256 threads
    if (blockIdx.x < 256) {
        // ---- subevent -> bf16 transpose, tile-major ----
        int j0 = blockIdx.x * 64;
        int jl = t >> 2;
        int sbase = t & 3;
        const float4* src = (const float4*)(sub + (size_t)(j0 + jl) * DIM);
        #pragma unroll
        for (int it = 0; it < 8; ++it) {
            int s = sbase + it * 4;
            float4 v = src[s];
            int d = s * 4;
            smT[d + 0][jl] = __float2bfloat16(v.x);
            smT[d + 1][jl] = __float2bfloat16(v.y);
            smT[d + 2][jl] = __float2bfloat16(v.z);
            smT[d + 3][jl] = __float2bfloat16(v.w);
        }
        __syncthreads();
        int d = t >> 1;
        int jh = (t & 1) * 32;
        uint4* dst = (uint4*)(g_ST + (size_t)blockIdx.x * (128 * 64) + d * 64 + jh);
        const uint4* s4 = (const uint4*)&smT[d][jh];
        dst[0] = s4[0]; dst[1] = s4[1]; dst[2] = s4[2]; dst[3] = s4[3];
    } else {
        // ---- projections, scaled by log2(e) ----
        const float L = 1.4426950408889634f;
        int gw = ((blockIdx.x - 256) * 256 + t) >> 5;
        int lane = t & 31;
        int nw = (96 * 256) >> 5;
        for (int r = gw; r < NSEVT + NEVT; r += nw) {
            const float* base;
            const float* wp;
            if (r < NSEVT) { base = sub + (size_t)r * DIM; wp = w; }
            else           { base = evt + (size_t)(r - NSEVT) * DIM; wp = w + DIM; }
            float4 v = ((const float4*)base)[lane];
            float4 ww = __ldg((const float4*)wp + lane);
            float dsum = v.x * ww.x + v.y * ww.y + v.z * ww.z + v.w * ww.w;
            #pragma unroll
            for (int o = 16; o; o >>= 1) dsum += __shfl_xor_sync(0xffffffffu, dsum, o);
            if (lane == 0) {
                if (r < NSEVT) g_sproj[r] = dsum * L;
                else           g_eproj[r - NSEVT] = dsum * L;
            }
        }
    }
}

// ---------------- kernel 2: warp-specialized fused softmax-GEMM + epilogue --
// grid 128 (64 row-tiles x 2 k-halves), 1024 threads (<=64 regs/thread).
// warps 0-15: consumers (ldmatrix + mma bf16, 32Mx32N each).
// warps 16-31: producers (coalesced adj stream, exp, smem ring fill, Z).
#define SP_OFF   0
#define BAR_OFF  32768
#define BCAST_OFF 33000
#define ST_OFF   33536
#define STAGE_SZ 36864
#define A_SZ     18432
#define NSTAGE   3
#define SMEM_BYTES (ST_OFF + NSTAGE * STAGE_SZ)

__global__ void __launch_bounds__(1024, 1)
main_kernel(const float* __restrict__ adj,
            const float* __restrict__ evt,
            float* __restrict__ out) {
    extern __shared__ char smem[];
    const int tid = threadIdx.x;
    const int wid = tid >> 5;
    const int lid = tid & 31;

    const int tile = blockIdx.x >> 1;
    const int kv_half = blockIdx.x & 1;
    const int i0 = tile * 128;
    const int k0 = kv_half * (NSEVT / 2);

    const uint32_t sb = smem_u32(smem);

    // cooperative sproj load (all 1024 threads)
    {
        float4* spd = (float4*)(smem + SP_OFF);
        const float4* sps = (const float4*)(g_sproj + k0);
        for (int i = tid; i < 2048; i += 1024) spd[i] = __ldg(sps + i);
    }
    if (tid == 0) {
        #pragma unroll
        for (int s = 0; s < NSTAGE; ++s) {
            mbar_init(sb + BAR_OFF + s * 16, 512);      // full[s]: 512 producers
            mbar_init(sb + BAR_OFF + s * 16 + 8, 512);  // empty[s]: 512 consumers
        }
    }
    __syncthreads();

    if (wid >= 16) {
        // =================== PRODUCER (coalesced) ===================
        const int pw = wid - 16;         // 0..15
        const int ptid = tid - 512;      // 0..511
        const int h = lid >> 4;          // half-warp
        const int c4 = lid & 15;         // float4 column slot within 64-col tile
        const int rbase = pw * 2 + h;    // 0..31; rows: i*32 + rbase, i<4

        const float4* a4p = (const float4*)(adj + (size_t)(i0 + rbase) * NSEVT + k0) + c4;
        const char* gstb = (const char*)g_ST + (size_t)(kv_half * 128) * 16384 + ptid * 16;
        const float4* sp4 = (const float4*)(smem + SP_OFF);

        float epArr[4];
        float zrow[4];
        #pragma unroll
        for (int i = 0; i < 4; ++i) {
            epArr[i] = g_eproj[i0 + i * 32 + rbase];
            zrow[i] = 0.f;
        }

        // B store: thread chunk j -> smem row (ptid>>3)+j*64, col (ptid&7)*16B
        const uint32_t bst_base = (uint32_t)(ptid >> 3) * 144u + (uint32_t)(ptid & 7) * 16u;
        // A store: row i*32+rbase at 144B rows
        const uint32_t ast_base = (uint32_t)rbase * 144u + (uint32_t)c4 * 8u;

        float4 areg[4];
        #pragma unroll
        for (int i = 0; i < 4; ++i) areg[i] = __ldg(a4p + (size_t)i * 131072);

        int st = 0, ph = 1;   // producer parity starts at 1: first empty-wait passes

        for (int kt = 0; kt < 128; ++kt) {
            // B tile loads (lane-contiguous, 2 x 16B per thread)
            uint4 bv[2];
            {
                const char* bsrc = gstb + (size_t)kt * 16384;
                bv[0] = __ldg((const uint4*)bsrc);
                bv[1] = __ldg((const uint4*)(bsrc + 8192));
            }

            float4 s = sp4[kt * 16 + c4];

            // exp compute into wpk (consumes areg), accumulate per-row Z
            uint2 wpk[4];
            #pragma unroll
            for (int i = 0; i < 4; ++i) {
                float4 a = areg[i];
                float ep = epArr[i];
                float c0 = ep + s.x, c1 = ep + s.y, c2 = ep + s.z, c3 = ep + s.w;
                float f0 = fmaxf(c0, 0.2f * c0), f1 = fmaxf(c1, 0.2f * c1);
                float f2 = fmaxf(c2, 0.2f * c2), f3 = fmaxf(c3, 0.2f * c3);
                float e0 = ex2f(a.x * f0), e1 = ex2f(a.y * f1);
                float e2 = ex2f(a.z * f2), e3 = ex2f(a.w * f3);
                zrow[i] += (e0 + e1) + (e2 + e3);
                wpk[i].x = pack_bf16x2(e0 * a.x, e1 * a.y);
                wpk[i].y = pack_bf16x2(e2 * a.z, e3 * a.w);
            }

            // prefetch next adj tile (areg free now)
            if (kt < 127) {
                const float4* anext = a4p + (kt + 1) * 16;
                #pragma unroll
                for (int i = 0; i < 4; ++i) areg[i] = __ldg(anext + (size_t)i * 131072);
            }

            // wait for stage free, store A + B, publish
            mbar_wait(sb + BAR_OFF + st * 16 + 8, ph);
            {
                char* Ab = smem + ST_OFF + (size_t)st * STAGE_SZ;
                char* Bb = Ab + A_SZ;
                #pragma unroll
                for (int i = 0; i < 4; ++i)
                    *reinterpret_cast<uint2*>(Ab + ast_base + i * (32 * 144)) = wpk[i];
                *reinterpret_cast<uint4*>(Bb + bst_base) = bv[0];
                *reinterpret_cast<uint4*>(Bb + bst_base + 64 * 144) = bv[1];
            }
            mbar_arrive(sb + BAR_OFF + st * 16);   // full[st]

            if (++st == NSTAGE) { st = 0; ph ^= 1; }
        }

        // Z: reduce across 16-lane column groups, one row per group
        #pragma unroll
        for (int i = 0; i < 4; ++i) {
            float z = zrow[i];
            z += __shfl_xor_sync(0xffffffffu, z, 8);
            z += __shfl_xor_sync(0xffffffffu, z, 4);
            z += __shfl_xor_sync(0xffffffffu, z, 2);
            z += __shfl_xor_sync(0xffffffffu, z, 1);
            if (c4 == 0)
                g_z[(size_t)kv_half * NEVT + i0 + i * 32 + rbase] = z;
        }

    } else {
        // =================== CONSUMER (32M x 32N per warp) ===================
        const int m0 = (wid & 3) * 32;
        const int n0 = (wid >> 2) * 32;
        const uint32_t a_radd = (uint32_t)(lid & 15) * 144u + ((uint32_t)(lid >> 4) * 8u) * 2u;
        const uint32_t b_radd = ((uint32_t)(lid & 7) + ((uint32_t)(lid >> 4) & 1u) * 8u) * 144u
                              + (((uint32_t)(lid >> 3) & 1u) * 8u) * 2u;

        float acc[2][4][4];
        #pragma unroll
        for (int mt = 0; mt < 2; ++mt)
            #pragma unroll
            for (int nb = 0; nb < 4; ++nb)
                #pragma unroll
                for (int q = 0; q < 4; ++q) acc[mt][nb][q] = 0.f;

        int st = 0, ph = 0;

        for (int kt = 0; kt < 128; ++kt) {
            mbar_wait(sb + BAR_OFF + st * 16, ph);   // full[st]

            const uint32_t Asb = sb + ST_OFF + (uint32_t)st * STAGE_SZ;
            const uint32_t Bsb = Asb + A_SZ;
            #pragma unroll
            for (int ks = 0; ks < 4; ++ks) {
                uint32_t afr[2][4];
                ldm_x4(Asb + (uint32_t)(m0)      * 144u + (uint32_t)(ks * 16) * 2u + a_radd, afr[0]);
                ldm_x4(Asb + (uint32_t)(m0 + 16) * 144u + (uint32_t)(ks * 16) * 2u + a_radd, afr[1]);
                uint32_t bfr[4][2];
                #pragma unroll
                for (int q = 0; q < 2; ++q) {
                    uint32_t t[4];
                    ldm_x4(Bsb + (uint32_t)(n0 + 16 * q) * 144u + (uint32_t)(ks * 16) * 2u + b_radd, t);
                    bfr[2 * q][0] = t[0]; bfr[2 * q][1] = t[1];
                    bfr[2 * q + 1][0] = t[2]; bfr[2 * q + 1][1] = t[3];
                }
                #pragma unroll
                for (int mt = 0; mt < 2; ++mt)
                    #pragma unroll
                    for (int nb = 0; nb < 4; ++nb)
                        mma16816(acc[mt][nb], afr[mt], bfr[nb]);
            }

            mbar_arrive(sb + BAR_OFF + st * 16 + 8);  // empty[st]
            if (++st == NSTAGE) { st = 0; ph ^= 1; }
        }

        // numerator partial writeout
        float* base = g_num + (size_t)kv_half * NEVT * DIM;
        const int r01 = i0 + m0 + (lid >> 2);
        const int colb = n0 + (lid & 3) * 2;
        #pragma unroll
        for (int mt = 0; mt < 2; ++mt) {
            #pragma unroll
            for (int nb = 0; nb < 4; ++nb) {
                int rr = r01 + mt * 16;
                int cc = colb + nb * 8;
                float2 lo = make_float2(acc[mt][nb][0], acc[mt][nb][1]);
                float2 hi = make_float2(acc[mt][nb][2], acc[mt][nb][3]);
                *reinterpret_cast<float2*>(base + (size_t)rr * DIM + cc) = lo;
                *reinterpret_cast<float2*>(base + (size_t)(rr + 8) * DIM + cc) = hi;
            }
        }
    }

    // =================== fused epilogue (split-K combine) ===================
    __threadfence();
    __syncthreads();
    if (tid == 0) {
        int old = atomicAdd(&g_flag[tile], 1);
        *reinterpret_cast<int*>(smem + BCAST_OFF) = old;
    }
    __syncthreads();
    if (*reinterpret_cast<int*>(smem + BCAST_OFF) == 1) {
        __threadfence();   // acquire partner CTA's g_num/g_z writes
        const float4* numA = (const float4*)g_num + (size_t)i0 * 32;
        const float4* numB = (const float4*)(g_num + (size_t)NEVT * DIM) + (size_t)i0 * 32;
        const float4* ev4  = (const float4*)evt + (size_t)i0 * 32;
        float4* o4 = (float4*)out + (size_t)i0 * 32;
        for (int idx = tid; idx < 128 * 32; idx += 1024) {
            int r = idx >> 5;
            float z = g_z[i0 + r] + g_z[NEVT + i0 + r];
            float inv = 1.0f / z;
            float4 n0 = numA[idx];
            float4 n1 = numB[idx];
            float4 e = __ldg(ev4 + idx);
            float4 o;
            o.x = (e.x + (n0.x + n1.x) * inv) * 0.5f;
            o.y = (e.y + (n0.y + n1.y) * inv) * 0.5f;
            o.z = (e.z + (n0.z + n1.z) * inv) * 0.5f;
            o.w = (e.w + (n0.w + n1.w) * inv) * 0.5f;
            o4[idx] = o;
        }
        if (tid == 0) g_flag[tile] = 0;   // reset for next graph replay
    }
}

// ---------------- launch ----------------------------------------------------
extern "C" void kernel_launch(void* const* d_in, const int* in_sizes, int n_in,
                              void* d_out, int out_size) {
    const float *adj = nullptr, *sub = nullptr, *evt = nullptr, *w = nullptr;
    for (int i = 0; i < n_in; ++i) {
        switch (in_sizes[i]) {
            case NEVT * NSEVT: adj = (const float*)d_in[i]; break;
            case NSEVT * DIM:  sub = (const float*)d_in[i]; break;
            case NEVT * DIM:   evt = (const float*)d_in[i]; break;
            case 2 * DIM:      w   = (const float*)d_in[i]; break;
            default: break;
        }
    }
    (void)out_size;

    static int configured = 0;
    if (!configured) {
        cudaFuncSetAttribute(main_kernel, cudaFuncAttributeMaxDynamicSharedMemorySize,
                             SMEM_BYTES);
        configured = 1;
    }

    pre_kernel<<<352, 256>>>(sub, evt, w);
    main_kernel<<<128, 1024, SMEM_BYTES>>>(adj, evt, (float*)d_out);
}